// round 1
// baseline (speedup 1.0000x reference)
#include <cuda_runtime.h>
#include <math.h>

#define H_IMG 256
#define W_IMG 256
#define TANFOV 0.7f
#define MAXN 4096
#define ALPHA_MIN (1.0f/255.0f)

// Scratch: sorted-by-z packed gaussian records
__device__ float4 g_bb[MAXN];   // xmin, xmax, ymin, ymax (conservative; culled => empty box)
__device__ float4 g_p1[MAXN];   // mx, my, conic_a, conic_b
__device__ float4 g_p2[MAXN];   // conic_c, opacity, z, pad
__device__ float4 g_cl[MAXN];   // r, g, b, pad

__global__ __launch_bounds__(1024) void gs_preprocess(
    const float* __restrict__ means,
    const float* __restrict__ opac,
    const float* __restrict__ colors,
    const float* __restrict__ scales,
    const float* __restrict__ rots,
    const float* __restrict__ vm,
    float* __restrict__ radii_out,
    int n)
{
    __shared__ float s_z[1024];
    const int i = threadIdx.x;
    const bool act = (i < n);

    const float fx = W_IMG / (2.0f * TANFOV);
    const float fy = H_IMG / (2.0f * TANFOV);

    const float R00=vm[0],R01=vm[1],R02=vm[2],t0=vm[3];
    const float R10=vm[4],R11=vm[5],R12=vm[6],t1=vm[7];
    const float R20=vm[8],R21=vm[9],R22=vm[10],t2=vm[11];

    float pz = 0.0f;
    float4 bb = make_float4(1e30f, -1e30f, 1e30f, -1e30f);
    float4 p1 = make_float4(0,0,0,0), p2 = make_float4(0,0,0,0), cl = make_float4(0,0,0,0);
    float radf = 0.0f;

    if (act) {
        float m0=means[3*i], m1=means[3*i+1], m2=means[3*i+2];
        float pxv = R00*m0 + R01*m1 + R02*m2 + t0;
        float pyv = R10*m0 + R11*m1 + R12*m2 + t1;
        pz        = R20*m0 + R21*m1 + R22*m2 + t2;
        float zc = fmaxf(pz, 1e-4f);
        float lim = 1.3f * TANFOV;
        float txc = fminf(fmaxf(pxv/zc, -lim), lim) * zc;
        float tyc = fminf(fmaxf(pyv/zc, -lim), lim) * zc;

        // quaternion -> rotation
        float q0=rots[4*i], q1=rots[4*i+1], q2=rots[4*i+2], q3=rots[4*i+3];
        float qn = rsqrtf(q0*q0 + q1*q1 + q2*q2 + q3*q3);
        q0*=qn; q1*=qn; q2*=qn; q3*=qn;
        float xx=q1*q1, yy=q2*q2, zz=q3*q3;
        float xy=q1*q2, xz=q1*q3, yz=q2*q3;
        float rx=q0*q1, ry=q0*q2, rz=q0*q3;
        float Q00=1.f-2.f*(yy+zz), Q01=2.f*(xy-rz),      Q02=2.f*(xz+ry);
        float Q10=2.f*(xy+rz),      Q11=1.f-2.f*(xx+zz), Q12=2.f*(yz-rx);
        float Q20=2.f*(xz-ry),      Q21=2.f*(yz+rx),     Q22=1.f-2.f*(xx+yy);
        float sx=scales[3*i], sy=scales[3*i+1], sz2=scales[3*i+2];
        float M00=Q00*sx, M01=Q01*sy, M02=Q02*sz2;
        float M10=Q10*sx, M11=Q11*sy, M12=Q12*sz2;
        float M20=Q20*sx, M21=Q21*sy, M22=Q22*sz2;
        float C00=M00*M00+M01*M01+M02*M02;
        float C01=M00*M10+M01*M11+M02*M12;
        float C02=M00*M20+M01*M21+M02*M22;
        float C11=M10*M10+M11*M11+M12*M12;
        float C12=M10*M20+M11*M21+M12*M22;
        float C22=M20*M20+M21*M21+M22*M22;
        float j00=fx/zc, j02=-fx*txc/(zc*zc);
        float j11=fy/zc, j12=-fy*tyc/(zc*zc);
        float T00=j00*R00+j02*R20, T01=j00*R01+j02*R21, T02=j00*R02+j02*R22;
        float T10=j11*R10+j12*R20, T11=j11*R11+j12*R21, T12=j11*R12+j12*R22;
        float u0=C00*T00+C01*T01+C02*T02;
        float u1=C01*T00+C11*T01+C12*T02;
        float u2=C02*T00+C12*T01+C22*T02;
        float v0=C00*T10+C01*T11+C02*T12;
        float v1=C01*T10+C11*T11+C12*T12;
        float v2=C02*T10+C12*T11+C22*T12;
        float a  = T00*u0 + T01*u1 + T02*u2 + 0.3f;
        float bq = T10*u0 + T11*u1 + T12*u2;
        float c  = T10*v0 + T11*v1 + T12*v2 + 0.3f;
        float det = a*c - bq*bq;
        float inv_det = 1.0f / fmaxf(det, 1e-12f);
        float cA = c*inv_det, cB = -bq*inv_det, cC = a*inv_det;
        float mid = 0.5f*(a + c);
        float lam1 = mid + sqrtf(fmaxf(mid*mid - det, 0.1f));
        radf = ceilf(3.0f * sqrtf(lam1));
        float mx = fx*pxv/zc + 0.5f*W_IMG - 0.5f;
        float my = fy*pyv/zc + 0.5f*H_IMG - 0.5f;
        bool valid = (pz > 0.2f) && (det > 0.0f);
        float op = opac[i];
        float sthr = 2.0f * logf(255.0f * op);   // alpha >= 1/255  <=>  Q <= sthr
        if (valid && sthr > 0.0f) {
            // bbox of level set; a,c >= 0.3 so sqrt args positive. Small safety margin.
            float hx = sqrtf(sthr * a) * 1.001f + 0.6f;
            float hy = sqrtf(sthr * c) * 1.001f + 0.6f;
            bb = make_float4(mx - hx, mx + hx, my - hy, my + hy);
        }
        p1 = make_float4(mx, my, cA, cB);
        p2 = make_float4(cC, op, pz, 0.0f);
        cl = make_float4(colors[3*i], colors[3*i+1], colors[3*i+2], 0.0f);
        s_z[i] = pz;
    }
    __syncthreads();
    if (act) {
        // stable rank (matches jnp.argsort)
        int rank = 0;
        for (int j = 0; j < n; j++) {
            float zj = s_z[j];
            rank += (zj < pz) || (zj == pz && j < i);
        }
        g_bb[rank] = bb; g_p1[rank] = p1; g_p2[rank] = p2; g_cl[rank] = cl;
        radii_out[i] = radf;  // radii in ORIGINAL order
    }
}

__global__ __launch_bounds__(256) void gs_raster(
    const float* __restrict__ bg, float* __restrict__ out, int n)
{
    __shared__ float4 sP1[256], sP2[256], sCl[256];
    __shared__ int sWcnt[8], sWoff[8], sTotal;

    const int tx = threadIdx.x, ty = threadIdx.y;
    const int tid = ty * 16 + tx;
    const int px = blockIdx.x * 16 + tx;
    const int py = blockIdx.y * 16 + ty;
    const float fpx = (float)px, fpy = (float)py;
    const float tX0 = (float)(blockIdx.x * 16), tX1 = tX0 + 15.0f;
    const float tY0 = (float)(blockIdx.y * 16), tY1 = tY0 + 15.0f;
    const int lane = tid & 31, wrp = tid >> 5;

    float T = 1.0f, aR = 0.0f, aG = 0.0f, aB = 0.0f, dep = 0.0f, mw = 0.0f;
    int cnt = 0;

    for (int base = 0; base < n; base += 256) {
        int g = base + tid;
        bool pred = false;
        if (g < n) {
            float4 bb = g_bb[g];
            pred = (bb.x <= tX1) && (bb.y >= tX0) && (bb.z <= tY1) && (bb.w >= tY0);
        }
        unsigned msk = __ballot_sync(0xffffffffu, pred);
        if (lane == 0) sWcnt[wrp] = __popc(msk);
        __syncthreads();
        if (tid == 0) {
            int acc = 0;
            #pragma unroll
            for (int w = 0; w < 8; w++) { sWoff[w] = acc; acc += sWcnt[w]; }
            sTotal = acc;
        }
        __syncthreads();
        if (pred) {
            int idx = sWoff[wrp] + __popc(msk & ((1u << lane) - 1u));
            sP1[idx] = g_p1[g];
            sP2[idx] = g_p2[g];
            sCl[idx] = g_cl[g];
        }
        __syncthreads();
        const int total = sTotal;
        for (int k = 0; k < total; k++) {
            float4 p1 = sP1[k], p2 = sP2[k];
            float dx = fpx - p1.x, dy = fpy - p1.y;
            float pw = -0.5f * (p1.z * dx * dx + p2.x * dy * dy) - p1.w * dx * dy;
            float al = fminf(0.99f, p2.y * __expf(fminf(pw, 0.0f)));
            if (pw <= 0.0f && al >= ALPHA_MIN) {
                float4 c4 = sCl[k];
                cnt++;
                float wv = al * T;
                aR += wv * c4.x; aG += wv * c4.y; aB += wv * c4.z;
                dep += wv * p2.z;
                mw = fmaxf(mw, wv);
                T *= (1.0f - al);
            }
        }
        __syncthreads();
    }

    const int HW = H_IMG * W_IMG;
    const int pix = py * W_IMG + px;
    out[3 * pix + 0] = aR + T * bg[0];
    out[3 * pix + 1] = aG + T * bg[1];
    out[3 * pix + 2] = aB + T * bg[2];
    float* o2 = out + 3 * HW + n;
    o2[pix]          = (float)cnt;   // out_observe
    o2[HW + pix]     = dep;          // out_plane_depth
    o2[2 * HW + pix] = mw;           // app_opacity
    o2[3 * HW + pix] = 1.0f - T;     // color_alpha
}

extern "C" void kernel_launch(void* const* d_in, const int* in_sizes, int n_in,
                              void* d_out, int out_size) {
    const float* means  = (const float*)d_in[0];
    const float* opac   = (const float*)d_in[1];
    const float* colors = (const float*)d_in[2];
    const float* scales = (const float*)d_in[3];
    const float* rots   = (const float*)d_in[4];
    const float* bg     = (const float*)d_in[5];
    const float* vm     = (const float*)d_in[6];
    const int n = in_sizes[0] / 3;
    float* out = (float*)d_out;

    gs_preprocess<<<1, 1024>>>(means, opac, colors, scales, rots, vm,
                               out + (size_t)3 * H_IMG * W_IMG, n);
    dim3 grid(W_IMG / 16, H_IMG / 16);
    dim3 block(16, 16);
    gs_raster<<<grid, block>>>(bg, out, n);
}

// round 2
// speedup vs baseline: 1.8294x; 1.8294x over previous
#include <cuda_runtime.h>
#include <math.h>

#define H_IMG 256
#define W_IMG 256
#define TANFOV 0.7f
#define ALPHA_MIN (1.0f/255.0f)
#define MAXG 512

__global__ __launch_bounds__(256) void gs_fused(
    const float* __restrict__ means,
    const float* __restrict__ opac,
    const float* __restrict__ colors,
    const float* __restrict__ scales,
    const float* __restrict__ rots,
    const float* __restrict__ bg,
    const float* __restrict__ vm,
    float* __restrict__ out, int n)
{
    __shared__ float4 sP1[MAXG + 4];  // mx, my, conicA, conicB
    __shared__ float4 sP2[MAXG + 4];  // conicC, opacity, z, pad
    __shared__ float4 sCl[MAXG + 4];  // r, g, b, pad
    __shared__ float  sZ[MAXG];
    __shared__ int    sIdx[MAXG];
    __shared__ int    sWcnt[8], sWoff[8];
    __shared__ int    sK;

    const int tid  = threadIdx.x;
    const int lane = tid & 31, wrp = tid >> 5;
    const int px = blockIdx.x * 16 + (tid & 15);
    const int py = blockIdx.y * 16 + (tid >> 4);
    const float tX0 = (float)(blockIdx.x * 16), tX1 = tX0 + 15.0f;
    const float tY0 = (float)(blockIdx.y * 16), tY1 = tY0 + 15.0f;

    const float fx = W_IMG / (2.0f * TANFOV);
    const float fy = H_IMG / (2.0f * TANFOV);
    const float R00 = vm[0], R01 = vm[1], R02 = vm[2],  t0 = vm[3];
    const float R10 = vm[4], R11 = vm[5], R12 = vm[6],  t1 = vm[7];
    const float R20 = vm[8], R21 = vm[9], R22 = vm[10], t2 = vm[11];

    const bool isB0 = (blockIdx.x == 0) && (blockIdx.y == 0);
    float* radii_out = out + (size_t)3 * H_IMG * W_IMG;

    if (tid == 0) sK = 0;
    __syncthreads();

    // ---------------- Phase A: per-tile preprocess + cull + ordered compaction ----
    for (int base = 0; base < n; base += 256) {
        int g = base + tid;
        bool pred = false;
        float4 p1v, p2v, clv; float zg = 0.0f;
        if (g < n) {
            float m0 = means[3*g], m1 = means[3*g+1], m2 = means[3*g+2];
            float pxv = R00*m0 + R01*m1 + R02*m2 + t0;
            float pyv = R10*m0 + R11*m1 + R12*m2 + t1;
            zg        = R20*m0 + R21*m1 + R22*m2 + t2;
            float zc = fmaxf(zg, 1e-4f);
            float lim = 1.3f * TANFOV;
            float txc = fminf(fmaxf(pxv/zc, -lim), lim) * zc;
            float tyc = fminf(fmaxf(pyv/zc, -lim), lim) * zc;

            float q0 = rots[4*g], q1 = rots[4*g+1], q2 = rots[4*g+2], q3 = rots[4*g+3];
            float qn = rsqrtf(q0*q0 + q1*q1 + q2*q2 + q3*q3);
            q0 *= qn; q1 *= qn; q2 *= qn; q3 *= qn;
            float xx = q1*q1, yy = q2*q2, zz = q3*q3;
            float xy = q1*q2, xz = q1*q3, yz = q2*q3;
            float rx = q0*q1, ry = q0*q2, rz = q0*q3;
            float Q00 = 1.f-2.f*(yy+zz), Q01 = 2.f*(xy-rz),      Q02 = 2.f*(xz+ry);
            float Q10 = 2.f*(xy+rz),     Q11 = 1.f-2.f*(xx+zz),  Q12 = 2.f*(yz-rx);
            float Q20 = 2.f*(xz-ry),     Q21 = 2.f*(yz+rx),      Q22 = 1.f-2.f*(xx+yy);
            float sx = scales[3*g], sy = scales[3*g+1], sz2 = scales[3*g+2];
            float M00 = Q00*sx, M01 = Q01*sy, M02 = Q02*sz2;
            float M10 = Q10*sx, M11 = Q11*sy, M12 = Q12*sz2;
            float M20 = Q20*sx, M21 = Q21*sy, M22 = Q22*sz2;
            float C00 = M00*M00 + M01*M01 + M02*M02;
            float C01 = M00*M10 + M01*M11 + M02*M12;
            float C02 = M00*M20 + M01*M21 + M02*M22;
            float C11 = M10*M10 + M11*M11 + M12*M12;
            float C12 = M10*M20 + M11*M21 + M12*M22;
            float C22 = M20*M20 + M21*M21 + M22*M22;
            float j00 = fx/zc, j02 = -fx*txc/(zc*zc);
            float j11 = fy/zc, j12 = -fy*tyc/(zc*zc);
            float T00 = j00*R00 + j02*R20, T01 = j00*R01 + j02*R21, T02 = j00*R02 + j02*R22;
            float T10 = j11*R10 + j12*R20, T11 = j11*R11 + j12*R21, T12 = j11*R12 + j12*R22;
            float u0 = C00*T00 + C01*T01 + C02*T02;
            float u1 = C01*T00 + C11*T01 + C12*T02;
            float u2 = C02*T00 + C12*T01 + C22*T02;
            float v0 = C00*T10 + C01*T11 + C02*T12;
            float v1 = C01*T10 + C11*T11 + C12*T12;
            float v2 = C02*T10 + C12*T11 + C22*T12;
            float a  = T00*u0 + T01*u1 + T02*u2 + 0.3f;
            float bq = T10*u0 + T11*u1 + T12*u2;
            float c  = T10*v0 + T11*v1 + T12*v2 + 0.3f;
            float det = a*c - bq*bq;
            float inv_det = 1.0f / fmaxf(det, 1e-12f);
            float cA = c*inv_det, cB = -bq*inv_det, cC = a*inv_det;
            float mid = 0.5f*(a + c);
            float lam1 = mid + sqrtf(fmaxf(mid*mid - det, 0.1f));
            float radf = ceilf(3.0f * sqrtf(lam1));
            float mx = fx*pxv/zc + 0.5f*W_IMG - 0.5f;
            float my = fy*pyv/zc + 0.5f*H_IMG - 0.5f;
            bool valid = (zg > 0.2f) && (det > 0.0f);
            float op = opac[g];
            float sthr = 2.0f * logf(255.0f * op);
            if (isB0) radii_out[g] = radf;
            if (valid && sthr > 0.0f) {
                float hx = sqrtf(sthr * a) * 1.001f + 0.6f;
                float hy = sqrtf(sthr * c) * 1.001f + 0.6f;
                pred = (mx - hx <= tX1) && (mx + hx >= tX0) &&
                       (my - hy <= tY1) && (my + hy >= tY0);
            }
            p1v = make_float4(mx, my, cA, cB);
            p2v = make_float4(cC, op, zg, 0.0f);
            clv = make_float4(colors[3*g], colors[3*g+1], colors[3*g+2], 0.0f);
        }
        unsigned msk = __ballot_sync(0xffffffffu, pred);
        if (lane == 0) sWcnt[wrp] = __popc(msk);
        __syncthreads();
        if (tid == 0) {
            int acc = sK;
            #pragma unroll
            for (int w = 0; w < 8; w++) { sWoff[w] = acc; acc += sWcnt[w]; }
            sK = acc;
        }
        __syncthreads();
        if (pred) {
            int idx = sWoff[wrp] + __popc(msk & ((1u << lane) - 1u));
            sP1[idx] = p1v; sP2[idx] = p2v; sCl[idx] = clv;
            sZ[idx] = zg; sIdx[idx] = g;
        }
        __syncthreads();
    }

    // ---------------- Phase B: stable z-rank permute of survivors ----------------
    const int k = sK;
    float4 r1a, r2a, cla, r1b, r2b, clb;
    float za = 0.f, zb = 0.f; int ia = 0, ib = 0;
    const bool ha = (tid < k), hb = (tid + 256 < k);
    if (ha) { r1a = sP1[tid]; r2a = sP2[tid]; cla = sCl[tid]; za = sZ[tid]; ia = sIdx[tid]; }
    if (hb) { int e = tid + 256; r1b = sP1[e]; r2b = sP2[e]; clb = sCl[e]; zb = sZ[e]; ib = sIdx[e]; }
    int ra = 0, rb = 0;
    for (int j = 0; j < k; j++) {
        float zj = sZ[j]; int ij = sIdx[j];
        ra += (zj < za) || (zj == za && ij < ia);
        rb += (zj < zb) || (zj == zb && ij < ib);
    }
    __syncthreads();
    if (ha) { sP1[ra] = r1a; sP2[ra] = r2a; sCl[ra] = cla; }
    if (hb) { sP1[rb] = r1b; sP2[rb] = r2b; sCl[rb] = clb; }
    if (tid < 4) {
        float4 z4 = make_float4(0.f, 0.f, 0.f, 0.f);
        sP1[k + tid] = z4; sP2[k + tid] = z4; sCl[k + tid] = z4;
    }
    __syncthreads();

    // ---------------- Phase C: ordered compositing, 4x unrolled, branchless ------
    const float fpx = (float)px, fpy = (float)py;
    float T = 1.0f, aR = 0.f, aG = 0.f, aB = 0.f, dep = 0.f, mw = 0.f;
    int cnt = 0;
    const int kpad = (k + 3) & ~3;
    for (int kk = 0; kk < kpad; kk += 4) {
        float al4[4], zv4[4];
        bool  kp4[4];
        #pragma unroll
        for (int j = 0; j < 4; j++) {
            float4 p1 = sP1[kk + j];
            float4 p2 = sP2[kk + j];
            float dx = fpx - p1.x, dy = fpy - p1.y;
            float pw = -0.5f * (p1.z * dx * dx + p2.x * dy * dy) - p1.w * dx * dy;
            float al = fminf(0.99f, p2.y * __expf(fminf(pw, 0.0f)));
            kp4[j] = (pw <= 0.0f) && (al >= ALPHA_MIN);
            al4[j] = al; zv4[j] = p2.z;
        }
        #pragma unroll
        for (int j = 0; j < 4; j++) {
            float a_eff = kp4[j] ? al4[j] : 0.0f;
            float4 c4 = sCl[kk + j];
            float wv = a_eff * T;
            aR = fmaf(wv, c4.x, aR);
            aG = fmaf(wv, c4.y, aG);
            aB = fmaf(wv, c4.z, aB);
            dep = fmaf(wv, zv4[j], dep);
            mw = fmaxf(mw, wv);
            cnt += kp4[j] ? 1 : 0;
            T *= (1.0f - a_eff);
        }
    }

    const int HW = H_IMG * W_IMG;
    const int pix = py * W_IMG + px;
    out[3 * pix + 0] = aR + T * bg[0];
    out[3 * pix + 1] = aG + T * bg[1];
    out[3 * pix + 2] = aB + T * bg[2];
    float* o2 = out + 3 * HW + n;
    o2[pix]          = (float)cnt;   // out_observe
    o2[HW + pix]     = dep;          // out_plane_depth
    o2[2 * HW + pix] = mw;           // app_opacity
    o2[3 * HW + pix] = 1.0f - T;     // color_alpha
}

extern "C" void kernel_launch(void* const* d_in, const int* in_sizes, int n_in,
                              void* d_out, int out_size) {
    const float* means  = (const float*)d_in[0];
    const float* opac   = (const float*)d_in[1];
    const float* colors = (const float*)d_in[2];
    const float* scales = (const float*)d_in[3];
    const float* rots   = (const float*)d_in[4];
    const float* bg     = (const float*)d_in[5];
    const float* vm     = (const float*)d_in[6];
    const int n = in_sizes[0] / 3;
    float* out = (float*)d_out;

    dim3 grid(W_IMG / 16, H_IMG / 16);
    gs_fused<<<grid, 256>>>(means, opac, colors, scales, rots, bg, vm, out, n);
}